// round 14
// baseline (speedup 1.0000x reference)
#include <cuda_runtime.h>
#include <cuda_fp16.h>
#include <cstdint>
#include <math.h>

#define BB 4
#define SS 2048
#define DD 1024

// ---------------------------------------------------------------------------
// Scratch (device globals — allocation-free per harness rules)
// All operands plain fp16 (1-pass scheme); fp32 accumulate in MMA.
// Calibrated error model: ~10 incoherent fp16-round components -> ~5.9e-4.
// ---------------------------------------------------------------------------
__device__ __half g_xh [(size_t)BB * SS * DD];       // x fp16    [8192][1024]
__device__ __half g_wqt[(size_t)DD * DD];            // Wq^T fp16 [1024][1024]
__device__ __half g_wkt[(size_t)DD * DD];
__device__ __half g_wvt[(size_t)DD * DD];
__device__ __half g_qh [(size_t)BB * SS * DD];       // q fp16
__device__ __half g_kh [(size_t)BB * SS * DD];       // k fp16
__device__ __half g_vh [(size_t)BB * SS * DD];       // v fp16
__device__ __half g_vt [(size_t)BB * DD * SS];       // v^T fp16 [b][1024][2048]
__device__ float  g_s  [(size_t)BB * SS * SS];       // raw scores fp32
__device__ __half g_ah [(size_t)BB * SS * SS];       // attn fp16 [b][2048][2048]

// ---------------------------------------------------------------------------
// PTX helpers (compute_103-safe: cp.async, ldmatrix, mma.sync only)
// ---------------------------------------------------------------------------
__device__ __forceinline__ void cp16(uint32_t dst, const void* src) {
    asm volatile("cp.async.cg.shared.global [%0], [%1], 16;\n" :: "r"(dst), "l"(src));
}
__device__ __forceinline__ uint32_t swz128(uint32_t off) { return off ^ ((off >> 3) & 0x70); }

__device__ __forceinline__ void ldsm4(uint32_t& r0, uint32_t& r1, uint32_t& r2, uint32_t& r3,
                                      uint32_t addr) {
    asm volatile("ldmatrix.sync.aligned.m8n8.x4.shared.b16 {%0,%1,%2,%3}, [%4];"
                 : "=r"(r0), "=r"(r1), "=r"(r2), "=r"(r3) : "r"(addr));
}

__device__ __forceinline__ void mma_f16(float c[4], const uint32_t a[4], const uint32_t b0,
                                        const uint32_t b1) {
    asm volatile(
        "mma.sync.aligned.m16n8k16.row.col.f32.f16.f16.f32 "
        "{%0,%1,%2,%3}, {%4,%5,%6,%7}, {%8,%9}, {%0,%1,%2,%3};\n"
        : "+f"(c[0]), "+f"(c[1]), "+f"(c[2]), "+f"(c[3])
        : "r"(a[0]), "r"(a[1]), "r"(a[2]), "r"(a[3]), "r"(b0), "r"(b1));
}

// ---------------------------------------------------------------------------
// BIG kernel: CTA tile 128x256, 256 threads = 8 warps of 64x64 (2m x 4n).
// 1-pass fp16, chunk = 64 k per barrier (A 16KB + B 32KB, swz128 rows),
// 3-stage cp.async (48KB/stage), 1 CTA/SM.
// sched 1: fused QKV — A=x; B = Wq^T/Wk^T/Wv^T (w = t/256); C fp16
// sched 2: scores QK^T — triangular list on 128x256 tiles (72/batch); C fp32
// ---------------------------------------------------------------------------
#define BIG_STAGE 49152
#define BIG_SMEM (3 * BIG_STAGE)     // 147456

__global__ __launch_bounds__(256, 1)
void gemm_big(int sched,
              const __half* __restrict__ A,
              const __half* __restrict__ B0,
              const __half* __restrict__ B1,
              const __half* __restrict__ B2,
              void* __restrict__ C0, void* __restrict__ C1, void* __restrict__ C2)
{
    extern __shared__ __align__(1024) char smem[];
    const uint32_t base0 = (uint32_t)__cvta_generic_to_shared(smem);

    const int tid  = threadIdx.x;
    const int wid  = tid >> 5;
    const int lane = tid & 31;
    const int wm   = wid >> 2;      // 0..1
    const int wn   = wid & 3;       // 0..3

    // ---- decode tile ----
    const int t = blockIdx.x;
    const __half *Ag, *Bg;
    void* Cv;
    int m0, n0, N_C, mode;
    const int rowL = DD, nC = DD / 64;
    if (sched == 1) {                       // fused QKV: 64 m-tiles x 4 n-tiles x 3
        const int w = t >> 8;
        const int r = t & 255;
        m0 = (r >> 2) * 128; n0 = (r & 3) * 256;
        Ag = A;
        Bg = (w == 0) ? B0 : ((w == 1) ? B1 : B2);
        Cv = (w == 0) ? C0 : ((w == 1) ? C1 : C2);
        mode = 1; N_C = DD;
    } else {                                // scores, triangular (72/batch)
        const int z  = t / 72;
        const int tt = t - z * 72;
        int r = 0, off = 0, col = 0;
        for (;; r++) {
            const int cnt = (r >> 1) + 1;
            if (off + cnt > tt) { col = tt - off; break; }
            off += cnt;
        }
        m0 = r * 128; n0 = col * 256;
        Ag = A  + (size_t)z * SS * DD;
        Bg = B0 + (size_t)z * SS * DD;
        Cv = (float*)C0 + (size_t)z * SS * SS;
        mode = 0; N_C = SS;
    }

    // ldmatrix base offsets (rows of 128B = 64 k, SW128 swizzle per use)
    const int mo  = ((lane >> 3) & 1) * 8 + (lane & 7);
    const int akb = ((lane >> 4) & 1) * 16;
    const int no  = ((lane >> 4) & 1) * 8 + (lane & 7);
    const int bkb = ((lane >> 3) & 1) * 16;
    uint32_t aO[4], bO[4];
    #pragma unroll
    for (int f = 0; f < 4; f++) {
        aO[f] = (uint32_t)((wm * 64 + f * 16 + mo) * 128 + akb);
        bO[f] = (uint32_t)((wn * 64 + f * 16 + no) * 128 + bkb);
    }

    float acc[4][8][4];
    #pragma unroll
    for (int i = 0; i < 4; i++)
        #pragma unroll
        for (int j = 0; j < 8; j++)
            #pragma unroll
            for (int q = 0; q < 4; q++) acc[i][j][q] = 0.0f;

    // chunk loader: A 128 rows + B 256 rows, 128B each.
    // tid<128: A row tid AND B row 128+tid; tid>=128: B row tid-128.
    auto load_chunk = [&](int c) {
        const int st = c % 3;
        const uint32_t aBase = base0 + st * BIG_STAGE;
        const uint32_t bBase = aBase + 16384;
        {
            const int isB = tid >> 7;
            const int row = tid & 127;
            const __half* src = (isB ? (Bg + (size_t)(n0 + row) * rowL)
                                     : (Ag + (size_t)(m0 + row) * rowL)) + c * 64;
            const uint32_t d  = isB ? bBase : aBase;
            const uint32_t ro = (uint32_t)row * 128;
            #pragma unroll
            for (int s8 = 0; s8 < 8; s8++)
                cp16(d + swz128(ro + s8 * 16), src + s8 * 8);
        }
        if (tid < 128) {
            const int row = tid + 128;
            const __half* src = Bg + (size_t)(n0 + row) * rowL + c * 64;
            const uint32_t ro = (uint32_t)row * 128;
            #pragma unroll
            for (int s8 = 0; s8 < 8; s8++)
                cp16(bBase + swz128(ro + s8 * 16), src + s8 * 8);
        }
        asm volatile("cp.async.commit_group;\n");
    };

    load_chunk(0);
    load_chunk(1);

    for (int c = 0; c < nC; ++c) {
        if (c + 1 < nC) asm volatile("cp.async.wait_group 1;\n" ::: "memory");
        else            asm volatile("cp.async.wait_group 0;\n" ::: "memory");
        __syncthreads();

        if (c + 2 < nC) load_chunk(c + 2);

        const uint32_t aB = base0 + (c % 3) * BIG_STAGE;
        const uint32_t bB = aB + 16384;

        #pragma unroll
        for (int ks = 0; ks < 4; ks++) {
            const uint32_t kso = (uint32_t)(ks * 32);
            uint32_t af[4][4], bf[4][4];
            #pragma unroll
            for (int f = 0; f < 4; f++)
                ldsm4(af[f][0], af[f][1], af[f][2], af[f][3], aB + swz128(aO[f] + kso));
            #pragma unroll
            for (int f = 0; f < 4; f++)
                ldsm4(bf[f][0], bf[f][1], bf[f][2], bf[f][3], bB + swz128(bO[f] + kso));
            #pragma unroll
            for (int im = 0; im < 4; im++)
                #pragma unroll
                for (int jn = 0; jn < 8; jn++)
                    mma_f16(acc[im][jn], af[im],
                            bf[jn >> 1][(jn & 1) * 2], bf[jn >> 1][(jn & 1) * 2 + 1]);
        }
    }

    // ---- epilogue ----
    #pragma unroll
    for (int im = 0; im < 4; im++) {
        const int r = m0 + wm * 64 + im * 16 + (lane >> 2);
        #pragma unroll
        for (int jn = 0; jn < 8; jn++) {
            const int cc = n0 + wn * 64 + jn * 8 + (lane & 3) * 2;
            if (mode == 0) {
                float* Cg = (float*)Cv;
                *(float2*)(Cg + (size_t)r * N_C + cc)       = make_float2(acc[im][jn][0], acc[im][jn][1]);
                *(float2*)(Cg + (size_t)(r + 8) * N_C + cc) = make_float2(acc[im][jn][2], acc[im][jn][3]);
            } else {
                __half* Cg = (__half*)Cv;
                #pragma unroll
                for (int hr = 0; hr < 2; hr++) {
                    const __half h0 = __float2half(acc[im][jn][hr * 2]);
                    const __half h1 = __float2half(acc[im][jn][hr * 2 + 1]);
                    *(__half2*)(Cg + (size_t)(r + hr * 8) * N_C + cc) = __halves2half2(h0, h1);
                }
            }
        }
    }
}

// ---------------------------------------------------------------------------
// AV kernel: 128x128, 128 threads = 4 warps of 64x64, 1-pass fp16,
// K clamped at the diagonal block, longest tiles first. C fp32.
// ---------------------------------------------------------------------------
#define AV_STAGE 32768
#define AV_SMEM (3 * AV_STAGE)

__global__ __launch_bounds__(128, 2)
void gemm_av(const __half* __restrict__ A,
             const __half* __restrict__ B,
             float* __restrict__ C)
{
    extern __shared__ __align__(1024) char smem[];
    const uint32_t base0 = (uint32_t)__cvta_generic_to_shared(smem);

    const int tid  = threadIdx.x;
    const int wid  = tid >> 5;
    const int lane = tid & 31;
    const int wm   = wid >> 1;
    const int wn   = wid & 1;

    const int t    = blockIdx.x;
    const int m    = 15 - (t >> 5);
    const int rest = t & 31;
    const int m0 = m * 128, n0 = (rest & 7) * 128;
    const int z  = rest >> 3;
    const __half* Ag = A + (size_t)z * SS * SS;
    const __half* Bg = B + (size_t)z * DD * SS;
    float* Cv = C + (size_t)z * SS * DD;
    const int nC = min(SS / 64, 2 * m + 2);

    const int mo  = ((lane >> 3) & 1) * 8 + (lane & 7);
    const int akb = ((lane >> 4) & 1) * 16;
    const int no  = ((lane >> 4) & 1) * 8 + (lane & 7);
    const int bkb = ((lane >> 3) & 1) * 16;
    uint32_t aO[4], bO[4];
    #pragma unroll
    for (int f = 0; f < 4; f++) {
        aO[f] = (uint32_t)((wm * 64 + f * 16 + mo) * 128 + akb);
        bO[f] = (uint32_t)((wn * 64 + f * 16 + no) * 128 + bkb);
    }

    float acc[4][8][4];
    #pragma unroll
    for (int i = 0; i < 4; i++)
        #pragma unroll
        for (int j = 0; j < 8; j++)
            #pragma unroll
            for (int q = 0; q < 4; q++) acc[i][j][q] = 0.0f;

    auto load_chunk = [&](int c) {
        const int st = c % 3;
        const uint32_t aBase = base0 + st * AV_STAGE;
        const uint32_t bBase = aBase + 16384;
        const __half* as = Ag + (size_t)(m0 + tid) * SS + c * 64;
        const __half* bs = Bg + (size_t)(n0 + tid) * SS + c * 64;
        const uint32_t ro = (uint32_t)tid * 128;
        #pragma unroll
        for (int s8 = 0; s8 < 8; s8++) {
            cp16(aBase + swz128(ro + s8 * 16), as + s8 * 8);
            cp16(bBase + swz128(ro + s8 * 16), bs + s8 * 8);
        }
        asm volatile("cp.async.commit_group;\n");
    };

    load_chunk(0);
    if (nC > 1) load_chunk(1);

    for (int c = 0; c < nC; ++c) {
        if (c + 1 < nC) asm volatile("cp.async.wait_group 1;\n" ::: "memory");
        else            asm volatile("cp.async.wait_group 0;\n" ::: "memory");
        __syncthreads();

        if (c + 2 < nC) load_chunk(c + 2);

        const uint32_t aB = base0 + (c % 3) * AV_STAGE;
        const uint32_t bB = aB + 16384;

        #pragma unroll
        for (int ks = 0; ks < 4; ks++) {
            const uint32_t kso = (uint32_t)(ks * 32);
            uint32_t af[4][4], bf[4][4];
            #pragma unroll
            for (int f = 0; f < 4; f++)
                ldsm4(af[f][0], af[f][1], af[f][2], af[f][3], aB + swz128(aO[f] + kso));
            #pragma unroll
            for (int f = 0; f < 4; f++)
                ldsm4(bf[f][0], bf[f][1], bf[f][2], bf[f][3], bB + swz128(bO[f] + kso));
            #pragma unroll
            for (int im = 0; im < 4; im++)
                #pragma unroll
                for (int jn = 0; jn < 8; jn++)
                    mma_f16(acc[im][jn], af[im],
                            bf[jn >> 1][(jn & 1) * 2], bf[jn >> 1][(jn & 1) * 2 + 1]);
        }
    }

    #pragma unroll
    for (int im = 0; im < 4; im++) {
        const int r = m0 + wm * 64 + im * 16 + (lane >> 2);
        #pragma unroll
        for (int jn = 0; jn < 8; jn++) {
            const int cc = n0 + wn * 64 + jn * 8 + (lane & 3) * 2;
            *(float2*)(Cv + (size_t)r * DD + cc)       = make_float2(acc[im][jn][0], acc[im][jn][1]);
            *(float2*)(Cv + (size_t)(r + 8) * DD + cc) = make_float2(acc[im][jn][2], acc[im][jn][3]);
        }
    }
}

// ---------------------------------------------------------------------------
// fp32 -> fp16 convert (x), 4 elements per thread
// ---------------------------------------------------------------------------
__global__ __launch_bounds__(256)
void conv_h(const float* __restrict__ src, __half* __restrict__ dst)
{
    const long long idx = ((long long)blockIdx.x * 256 + threadIdx.x) * 4;
    const float4 v = *(const float4*)(src + idx);
    __half2* o = (__half2*)(dst + idx);
    o[0] = __halves2half2(__float2half(v.x), __float2half(v.y));
    o[1] = __halves2half2(__float2half(v.z), __float2half(v.w));
}

// ---------------------------------------------------------------------------
// Merged weight transpose: fp32 [D][D] -> fp16 [D][D], 3 weights via z.
// ---------------------------------------------------------------------------
__global__ __launch_bounds__(256)
void transposeW(const float* __restrict__ s0, const float* __restrict__ s1,
                const float* __restrict__ s2,
                __half* __restrict__ d0, __half* __restrict__ d1,
                __half* __restrict__ d2)
{
    __shared__ float tile[32][33];
    const int z = blockIdx.z;
    const float* src = (z == 0) ? s0 : ((z == 1) ? s1 : s2);
    __half*      dst = (z == 0) ? d0 : ((z == 1) ? d1 : d2);
    const int r0 = blockIdx.y * 32, c0 = blockIdx.x * 32;
    const int tx = threadIdx.x & 31;
    const int ty = threadIdx.x >> 5;

    #pragma unroll
    for (int dy = 0; dy < 32; dy += 8)
        tile[ty + dy][tx] = src[(size_t)(r0 + ty + dy) * DD + c0 + tx];
    __syncthreads();

    #pragma unroll
    for (int dy = 0; dy < 32; dy += 8) {
        const int c = c0 + ty + dy;
        const int r = r0 + tx;
        dst[(size_t)c * DD + r] = __float2half(tile[tx][ty + dy]);
    }
}

// ---------------------------------------------------------------------------
// v transpose: fp16 [S][D] per batch -> fp16 [D][S]
// ---------------------------------------------------------------------------
__global__ __launch_bounds__(256)
void transposeV(const __half* __restrict__ src, __half* __restrict__ dst)
{
    __shared__ __half tile[32][40];
    src += (size_t)blockIdx.z * SS * DD;
    dst += (size_t)blockIdx.z * DD * SS;
    const int r0 = blockIdx.y * 32, c0 = blockIdx.x * 32;
    const int tx = threadIdx.x & 31;
    const int ty = threadIdx.x >> 5;

    #pragma unroll
    for (int dy = 0; dy < 32; dy += 8)
        tile[ty + dy][tx] = src[(size_t)(r0 + ty + dy) * DD + c0 + tx];
    __syncthreads();

    #pragma unroll
    for (int dy = 0; dy < 32; dy += 8) {
        const int c = c0 + ty + dy;
        const int r = r0 + tx;
        dst[(size_t)c * SS + r] = tile[tx][ty + dy];
    }
}

// ---------------------------------------------------------------------------
// Vectorized causal softmax -> fp16 attn (arithmetic masking, 4-wide).
// Lz = diagonal-block end (multiple of 128); AV K-clamp never reads past it.
// ---------------------------------------------------------------------------
__global__ __launch_bounds__(256)
void softmax1(const float* __restrict__ Sc, __half* __restrict__ Ah,
              int S, float scale)
{
    const long long row = blockIdx.x;            // b*S + i
    const int i = (int)(row % S);
    const float* p = Sc + row * (long long)S;
    __half* out = Ah + row * (long long)S;
    const int Lz = ((i >> 7) + 1) << 7;

    const int tid  = threadIdx.x;
    const int lane = tid & 31;
    const int wid  = tid >> 5;
    __shared__ float red[32];

    float mx = -INFINITY;
    for (int j = tid * 4; j < Lz; j += 1024) {
        float4 v = *(const float4*)(p + j);
        if (j + 0 > i) v.x = -INFINITY;
        if (j + 1 > i) v.y = -INFINITY;
        if (j + 2 > i) v.z = -INFINITY;
        if (j + 3 > i) v.w = -INFINITY;
        mx = fmaxf(mx, fmaxf(fmaxf(v.x, v.y), fmaxf(v.z, v.w)));
    }
    #pragma unroll
    for (int o = 16; o; o >>= 1) mx = fmaxf(mx, __shfl_xor_sync(0xffffffffu, mx, o));
    if (lane == 0) red[wid] = mx;
    __syncthreads();
    if (tid == 0) {
        float m = red[0];
        #pragma unroll
        for (int w = 1; w < 8; w++) m = fmaxf(m, red[w]);
        red[0] = m;
    }
    __syncthreads();
    mx = red[0];
    __syncthreads();

    float e[8];
    float sum = 0.0f;
    int cnt = 0;
    for (int j = tid * 4; j < Lz; j += 1024) {
        float4 v = *(const float4*)(p + j);
        const float e0 = (j + 0 <= i) ? __expf((v.x - mx) * scale) : 0.0f;
        const float e1 = (j + 1 <= i) ? __expf((v.y - mx) * scale) : 0.0f;
        const float e2 = (j + 2 <= i) ? __expf((v.z - mx) * scale) : 0.0f;
        const float e3 = (j + 3 <= i) ? __expf((v.w - mx) * scale) : 0.0f;
        e[cnt + 0] = e0; e[cnt + 1] = e1; e[cnt + 2] = e2; e[cnt + 3] = e3;
        cnt += 4;
        sum += (e0 + e1) + (e2 + e3);
    }
    #pragma unroll
    for (int o = 16; o; o >>= 1) sum += __shfl_xor_sync(0xffffffffu, sum, o);
    if (lane == 0) red[wid] = sum;
    __syncthreads();
    if (tid == 0) {
        float s = red[0];
        #pragma unroll
        for (int w = 1; w < 8; w++) s += red[w];
        red[0] = s;
    }
    __syncthreads();
    const float inv = 1.0f / red[0];

    cnt = 0;
    for (int j = tid * 4; j < Lz; j += 1024) {
        __half2* o2 = (__half2*)(out + j);
        o2[0] = __halves2half2(__float2half(e[cnt + 0] * inv),
                               __float2half(e[cnt + 1] * inv));
        o2[1] = __halves2half2(__float2half(e[cnt + 2] * inv),
                               __float2half(e[cnt + 3] * inv));
        cnt += 4;
    }
}

// ---------------------------------------------------------------------------
extern "C" void kernel_launch(void* const* d_in, const int* in_sizes, int n_in,
                              void* d_out, int out_size)
{
    (void)in_sizes; (void)n_in; (void)out_size;
    const float* x  = (const float*)d_in[0];
    const float* Wq = (const float*)d_in[1];
    const float* Wk = (const float*)d_in[2];
    const float* Wv = (const float*)d_in[3];
    float* out = (float*)d_out;

    __half *xh, *wqt, *wkt, *wvt, *qh, *kh, *vh, *vt, *ah;
    float *s;
    cudaGetSymbolAddress((void**)&xh,  g_xh);
    cudaGetSymbolAddress((void**)&wqt, g_wqt);
    cudaGetSymbolAddress((void**)&wkt, g_wkt);
    cudaGetSymbolAddress((void**)&wvt, g_wvt);
    cudaGetSymbolAddress((void**)&qh,  g_qh);
    cudaGetSymbolAddress((void**)&kh,  g_kh);
    cudaGetSymbolAddress((void**)&vh,  g_vh);
    cudaGetSymbolAddress((void**)&vt,  g_vt);
    cudaGetSymbolAddress((void**)&s,   g_s);
    cudaGetSymbolAddress((void**)&ah,  g_ah);

    cudaFuncSetAttribute(gemm_big, cudaFuncAttributeMaxDynamicSharedMemorySize, BIG_SMEM);
    cudaFuncSetAttribute(gemm_av,  cudaFuncAttributeMaxDynamicSharedMemorySize, AV_SMEM);

    const int B = BB, S = SS, D = DD;
    const long long MS = (long long)B * S;   // 8192

    // launch 0: x -> fp16 (4-wide)
    conv_h<<<(int)(MS * D / 1024), 256>>>(x, xh);

    // launch 1: merged weight transposes -> fp16
    {
        dim3 tg(D / 32, D / 32, 3);
        transposeW<<<tg, 256>>>(Wq, Wk, Wv, wqt, wkt, wvt);
    }

    // launch 2: fused QKV (768 tiles of 128x256) -> q/k/v fp16
    gemm_big<<<768, 256, BIG_SMEM>>>(1, xh, wqt, wkt, wvt, qh, kh, vh);

    // launch 3 (ncu-captured): scores = Q K^T, triangular 128x256 tiles
    gemm_big<<<72 * B, 256, BIG_SMEM>>>(2, qh, kh, nullptr, nullptr,
                                        s, nullptr, nullptr);

    // launch 4: v transpose (fp16 -> fp16)
    {
        dim3 tg(D / 32, S / 32, B);
        transposeV<<<tg, 256>>>(vh, vt);
    }

    // launch 5: vectorized softmax -> fp16 attn
    softmax1<<<B * S, 256>>>(s, ah, S, 0.03125f);

    // launch 6: out = attn @ V (K-clamped, longest tiles first)
    gemm_av<<<16 * 8 * B, 128, AV_SMEM>>>(ah, vt, out);
}

// round 15
// speedup vs baseline: 1.5263x; 1.5263x over previous
#include <cuda_runtime.h>
#include <cuda_fp16.h>
#include <cstdint>
#include <math.h>

#define BB 4
#define SS 2048
#define DD 1024

// ---------------------------------------------------------------------------
// Scratch (device globals — allocation-free per harness rules)
// All operands plain fp16 (1-pass scheme); fp32 accumulate in MMA.
// Calibrated error model: ~10 incoherent fp16-round components -> ~5.9e-4.
// ---------------------------------------------------------------------------
__device__ __half g_xh [(size_t)BB * SS * DD];       // x fp16    [8192][1024]
__device__ __half g_wqt[(size_t)DD * DD];            // Wq^T fp16 [1024][1024]
__device__ __half g_wkt[(size_t)DD * DD];
__device__ __half g_wvt[(size_t)DD * DD];
__device__ __half g_qh [(size_t)BB * SS * DD];       // q fp16
__device__ __half g_kh [(size_t)BB * SS * DD];       // k fp16
__device__ __half g_vt [(size_t)BB * DD * SS];       // v^T fp16 [b][1024][2048]
__device__ float  g_s  [(size_t)BB * SS * SS];       // raw scores fp32
__device__ __half g_ah [(size_t)BB * SS * SS];       // attn fp16 [b][2048][2048]

// ---------------------------------------------------------------------------
// PTX helpers (compute_103-safe: cp.async, ldmatrix, mma.sync only)
// ---------------------------------------------------------------------------
__device__ __forceinline__ void cp16(uint32_t dst, const void* src) {
    asm volatile("cp.async.cg.shared.global [%0], [%1], 16;\n" :: "r"(dst), "l"(src));
}
__device__ __forceinline__ uint32_t swz128(uint32_t off) { return off ^ ((off >> 3) & 0x70); }

__device__ __forceinline__ void ldsm4(uint32_t& r0, uint32_t& r1, uint32_t& r2, uint32_t& r3,
                                      uint32_t addr) {
    asm volatile("ldmatrix.sync.aligned.m8n8.x4.shared.b16 {%0,%1,%2,%3}, [%4];"
                 : "=r"(r0), "=r"(r1), "=r"(r2), "=r"(r3) : "r"(addr));
}

__device__ __forceinline__ void mma_f16(float c[4], const uint32_t a[4], const uint32_t b0,
                                        const uint32_t b1) {
    asm volatile(
        "mma.sync.aligned.m16n8k16.row.col.f32.f16.f16.f32 "
        "{%0,%1,%2,%3}, {%4,%5,%6,%7}, {%8,%9}, {%0,%1,%2,%3};\n"
        : "+f"(c[0]), "+f"(c[1]), "+f"(c[2]), "+f"(c[3])
        : "r"(a[0]), "r"(a[1]), "r"(a[2]), "r"(a[3]), "r"(b0), "r"(b1));
}

// ---------------------------------------------------------------------------
// 1-pass fp16 GEMM: C[m][n] = sum_k A[m][k] * B[n][k], fp32 accumulate.
// CTA tile 128x128, chunk = 64 k per barrier (A 16KB + B 16KB, swz128 rows),
// 3-stage cp.async, 128 threads = 4 warps of 64x64, ldmatrix.x4 fragments.
// sched 1: fused QKV — A=x; B = Wq^T/Wk^T/Wv^T (w=t>>9);
//          q/k -> fp16 rows (mode 1); v -> fp16 TRANSPOSED via SMEM bounce
//          (mode 2) directly into v^T [b][d][S] — no separate transpose pass.
// sched 2: scores QK^T — triangular causal list (136/batch); C fp32
// sched 3: attn @ V — K clamped at diagonal block, longest-first; C fp32
// ---------------------------------------------------------------------------
#define STAGE1 32768
#define GEMM_SMEM (3 * STAGE1)       // 98304

__global__ __launch_bounds__(128, 2)
void gemm1p(int sched,
            const __half* __restrict__ A,
            const __half* __restrict__ B0,
            const __half* __restrict__ B1,
            const __half* __restrict__ B2,
            void* __restrict__ C0, void* __restrict__ C1, void* __restrict__ C2)
{
    extern __shared__ __align__(1024) char smem[];
    const uint32_t base0 = (uint32_t)__cvta_generic_to_shared(smem);

    const int tid  = threadIdx.x;
    const int wid  = tid >> 5;
    const int lane = tid & 31;
    const int wm   = wid >> 1;      // 0..1
    const int wn   = wid & 1;       // 0..1

    // ---- decode tile ----
    const int t = blockIdx.x;
    const __half *Ag, *Bg;
    void* Cv;
    int m0, n0, N_C, rowA, rowB, nC, mode;
    if (sched == 1) {                       // fused QKV
        const int w = t >> 9;
        const int r = t & 511;
        m0 = (r >> 3) * 128; n0 = (r & 7) * 128;
        Ag = A;
        Bg = (w == 0) ? B0 : ((w == 1) ? B1 : B2);
        Cv = (w == 0) ? C0 : ((w == 1) ? C1 : C2);
        mode = (w == 2) ? 2 : 1;
        N_C = DD; rowA = DD; rowB = DD; nC = DD / 64;
    } else if (sched == 2) {                // scores, triangular decode
        const int z  = t / 136;
        const int tt = t - z * 136;
        int r = (int)floorf((sqrtf(8.0f * tt + 1.0f) - 1.0f) * 0.5f);
        while ((r + 1) * (r + 2) / 2 <= tt) r++;
        while (r * (r + 1) / 2 > tt) r--;
        const int c = tt - r * (r + 1) / 2;
        m0 = r * 128; n0 = c * 128;
        Ag = A  + (size_t)z * SS * DD;
        Bg = B0 + (size_t)z * SS * DD;
        Cv = (float*)C0 + (size_t)z * SS * SS;
        mode = 0; N_C = SS; rowA = DD; rowB = DD; nC = DD / 64;
    } else {                                // attn @ V, longest-first
        const int m    = 15 - (t >> 5);
        const int rest = t & 31;
        m0 = m * 128; n0 = (rest & 7) * 128;
        const int z = rest >> 3;
        Ag = A  + (size_t)z * SS * SS;
        Bg = B0 + (size_t)z * DD * SS;
        Cv = (float*)C0 + (size_t)z * SS * DD;
        mode = 0; N_C = DD; rowA = SS; rowB = SS;
        nC = min(SS / 64, 2 * m + 2);
    }

    // ldmatrix base offsets (rows of 128B = 64 k-cols, SW128 swizzle per use)
    const int mo  = ((lane >> 3) & 1) * 8 + (lane & 7);
    const int akb = ((lane >> 4) & 1) * 16;
    const int no  = ((lane >> 4) & 1) * 8 + (lane & 7);
    const int bkb = ((lane >> 3) & 1) * 16;
    uint32_t aO[4], bO[4];
    #pragma unroll
    for (int f = 0; f < 4; f++) {
        aO[f] = (uint32_t)((wm * 64 + f * 16 + mo) * 128 + akb);
        bO[f] = (uint32_t)((wn * 64 + f * 16 + no) * 128 + bkb);
    }

    float acc[4][8][4];
    #pragma unroll
    for (int i = 0; i < 4; i++)
        #pragma unroll
        for (int j = 0; j < 8; j++)
            #pragma unroll
            for (int q = 0; q < 4; q++) acc[i][j][q] = 0.0f;

    // chunk loader: thread t loads A row m0+t and B row n0+t (128B = 64 k each)
    auto load_chunk = [&](int c) {
        const int st = c % 3;
        const uint32_t aBase = base0 + st * STAGE1;
        const uint32_t bBase = aBase + 16384;
        const __half* as = Ag + (size_t)(m0 + tid) * rowA + c * 64;
        const __half* bs = Bg + (size_t)(n0 + tid) * rowB + c * 64;
        const uint32_t ro = (uint32_t)tid * 128;
        #pragma unroll
        for (int s8 = 0; s8 < 8; s8++) {
            cp16(aBase + swz128(ro + s8 * 16), as + s8 * 8);
            cp16(bBase + swz128(ro + s8 * 16), bs + s8 * 8);
        }
        asm volatile("cp.async.commit_group;\n");
    };

    load_chunk(0);
    if (nC > 1) load_chunk(1);

    for (int c = 0; c < nC; ++c) {
        if (c + 1 < nC) asm volatile("cp.async.wait_group 1;\n" ::: "memory");
        else            asm volatile("cp.async.wait_group 0;\n" ::: "memory");
        __syncthreads();

        if (c + 2 < nC) load_chunk(c + 2);

        const uint32_t aB = base0 + (c % 3) * STAGE1;
        const uint32_t bB = aB + 16384;

        #pragma unroll
        for (int ks = 0; ks < 4; ks++) {
            const uint32_t kso = (uint32_t)(ks * 32);
            uint32_t af[4][4], bf[4][4];
            #pragma unroll
            for (int f = 0; f < 4; f++)
                ldsm4(af[f][0], af[f][1], af[f][2], af[f][3], aB + swz128(aO[f] + kso));
            #pragma unroll
            for (int f = 0; f < 4; f++)
                ldsm4(bf[f][0], bf[f][1], bf[f][2], bf[f][3], bB + swz128(bO[f] + kso));
            #pragma unroll
            for (int im = 0; im < 4; im++)
                #pragma unroll
                for (int jn = 0; jn < 8; jn++)
                    mma_f16(acc[im][jn], af[im],
                            bf[jn >> 1][(jn & 1) * 2], bf[jn >> 1][(jn & 1) * 2 + 1]);
        }
    }

    // ---- epilogue ----
    if (mode == 2) {
        // v tile: fp16 + transpose via SMEM bounce -> v^T [b][d][S].
        __syncthreads();                       // stage smem now free
        __half* tf = (__half*)smem;            // [128 d-rows][136 pad] halves
        #pragma unroll
        for (int im = 0; im < 4; im++) {
            #pragma unroll
            for (int jn = 0; jn < 8; jn++) {
                #pragma unroll
                for (int hr = 0; hr < 2; hr++) {
                    const int rl = wm * 64 + im * 16 + (lane >> 2) + hr * 8;
                    const int cl = wn * 64 + jn * 8 + (lane & 3) * 2;
                    tf[(size_t)(cl + 0) * 136 + rl] = __float2half(acc[im][jn][hr * 2 + 0]);
                    tf[(size_t)(cl + 1) * 136 + rl] = __float2half(acc[im][jn][hr * 2 + 1]);
                }
            }
        }
        __syncthreads();
        const int b   = m0 >> 11;
        const int s0l = m0 & 2047;
        __half* dst = (__half*)Cv + ((size_t)b * DD + n0 + tid) * SS + s0l;
        const uint4* srcv = (const uint4*)(tf + (size_t)tid * 136);
        uint4* dstv = (uint4*)dst;
        #pragma unroll
        for (int k = 0; k < 16; k++) dstv[k] = srcv[k];
        return;
    }

    #pragma unroll
    for (int im = 0; im < 4; im++) {
        const int r = m0 + wm * 64 + im * 16 + (lane >> 2);
        #pragma unroll
        for (int jn = 0; jn < 8; jn++) {
            const int cc = n0 + wn * 64 + jn * 8 + (lane & 3) * 2;
            if (mode == 0) {
                float* Cg = (float*)Cv;
                *(float2*)(Cg + (size_t)r * N_C + cc)       = make_float2(acc[im][jn][0], acc[im][jn][1]);
                *(float2*)(Cg + (size_t)(r + 8) * N_C + cc) = make_float2(acc[im][jn][2], acc[im][jn][3]);
            } else {
                __half* Cg = (__half*)Cv;
                #pragma unroll
                for (int hr = 0; hr < 2; hr++) {
                    const __half h0 = __float2half(acc[im][jn][hr * 2]);
                    const __half h1 = __float2half(acc[im][jn][hr * 2 + 1]);
                    *(__half2*)(Cg + (size_t)(r + hr * 8) * N_C + cc) = __halves2half2(h0, h1);
                }
            }
        }
    }
}

// ---------------------------------------------------------------------------
// fp32 -> fp16 convert (x), 4 elements per thread
// ---------------------------------------------------------------------------
__global__ __launch_bounds__(256)
void conv_h(const float* __restrict__ src, __half* __restrict__ dst)
{
    const long long idx = ((long long)blockIdx.x * 256 + threadIdx.x) * 4;
    const float4 v = *(const float4*)(src + idx);
    __half2* o = (__half2*)(dst + idx);
    o[0] = __halves2half2(__float2half(v.x), __float2half(v.y));
    o[1] = __halves2half2(__float2half(v.z), __float2half(v.w));
}

// ---------------------------------------------------------------------------
// Merged weight transpose: fp32 [D][D] -> fp16 [D][D], 3 weights via z.
// ---------------------------------------------------------------------------
__global__ __launch_bounds__(256)
void transposeW(const float* __restrict__ s0, const float* __restrict__ s1,
                const float* __restrict__ s2,
                __half* __restrict__ d0, __half* __restrict__ d1,
                __half* __restrict__ d2)
{
    __shared__ float tile[32][33];
    const int z = blockIdx.z;
    const float* src = (z == 0) ? s0 : ((z == 1) ? s1 : s2);
    __half*      dst = (z == 0) ? d0 : ((z == 1) ? d1 : d2);
    const int r0 = blockIdx.y * 32, c0 = blockIdx.x * 32;
    const int tx = threadIdx.x & 31;
    const int ty = threadIdx.x >> 5;

    #pragma unroll
    for (int dy = 0; dy < 32; dy += 8)
        tile[ty + dy][tx] = src[(size_t)(r0 + ty + dy) * DD + c0 + tx];
    __syncthreads();

    #pragma unroll
    for (int dy = 0; dy < 32; dy += 8) {
        const int c = c0 + ty + dy;
        const int r = r0 + tx;
        dst[(size_t)c * DD + r] = __float2half(tile[tx][ty + dy]);
    }
}

// ---------------------------------------------------------------------------
// Vectorized causal softmax -> fp16 attn (arithmetic masking, 4-wide).
// Lz = diagonal-block end (multiple of 128); AV K-clamp never reads past it.
// ---------------------------------------------------------------------------
__global__ __launch_bounds__(256)
void softmax1(const float* __restrict__ Sc, __half* __restrict__ Ah,
              int S, float scale)
{
    const long long row = blockIdx.x;            // b*S + i
    const int i = (int)(row % S);
    const float* p = Sc + row * (long long)S;
    __half* out = Ah + row * (long long)S;
    const int Lz = ((i >> 7) + 1) << 7;

    const int tid  = threadIdx.x;
    const int lane = tid & 31;
    const int wid  = tid >> 5;
    __shared__ float red[32];

    float mx = -INFINITY;
    for (int j = tid * 4; j < Lz; j += 1024) {
        float4 v = *(const float4*)(p + j);
        if (j + 0 > i) v.x = -INFINITY;
        if (j + 1 > i) v.y = -INFINITY;
        if (j + 2 > i) v.z = -INFINITY;
        if (j + 3 > i) v.w = -INFINITY;
        mx = fmaxf(mx, fmaxf(fmaxf(v.x, v.y), fmaxf(v.z, v.w)));
    }
    #pragma unroll
    for (int o = 16; o; o >>= 1) mx = fmaxf(mx, __shfl_xor_sync(0xffffffffu, mx, o));
    if (lane == 0) red[wid] = mx;
    __syncthreads();
    if (tid == 0) {
        float m = red[0];
        #pragma unroll
        for (int w = 1; w < 8; w++) m = fmaxf(m, red[w]);
        red[0] = m;
    }
    __syncthreads();
    mx = red[0];
    __syncthreads();

    float e[8];
    float sum = 0.0f;
    int cnt = 0;
    for (int j = tid * 4; j < Lz; j += 1024) {
        float4 v = *(const float4*)(p + j);
        const float e0 = (j + 0 <= i) ? __expf((v.x - mx) * scale) : 0.0f;
        const float e1 = (j + 1 <= i) ? __expf((v.y - mx) * scale) : 0.0f;
        const float e2 = (j + 2 <= i) ? __expf((v.z - mx) * scale) : 0.0f;
        const float e3 = (j + 3 <= i) ? __expf((v.w - mx) * scale) : 0.0f;
        e[cnt + 0] = e0; e[cnt + 1] = e1; e[cnt + 2] = e2; e[cnt + 3] = e3;
        cnt += 4;
        sum += (e0 + e1) + (e2 + e3);
    }
    #pragma unroll
    for (int o = 16; o; o >>= 1) sum += __shfl_xor_sync(0xffffffffu, sum, o);
    if (lane == 0) red[wid] = sum;
    __syncthreads();
    if (tid == 0) {
        float s = red[0];
        #pragma unroll
        for (int w = 1; w < 8; w++) s += red[w];
        red[0] = s;
    }
    __syncthreads();
    const float inv = 1.0f / red[0];

    cnt = 0;
    for (int j = tid * 4; j < Lz; j += 1024) {
        __half2* o2 = (__half2*)(out + j);
        o2[0] = __halves2half2(__float2half(e[cnt + 0] * inv),
                               __float2half(e[cnt + 1] * inv));
        o2[1] = __halves2half2(__float2half(e[cnt + 2] * inv),
                               __float2half(e[cnt + 3] * inv));
        cnt += 4;
    }
}

// ---------------------------------------------------------------------------
extern "C" void kernel_launch(void* const* d_in, const int* in_sizes, int n_in,
                              void* d_out, int out_size)
{
    (void)in_sizes; (void)n_in; (void)out_size;
    const float* x  = (const float*)d_in[0];
    const float* Wq = (const float*)d_in[1];
    const float* Wk = (const float*)d_in[2];
    const float* Wv = (const float*)d_in[3];
    float* out = (float*)d_out;

    __half *xh, *wqt, *wkt, *wvt, *qh, *kh, *vt, *ah;
    float *s;
    cudaGetSymbolAddress((void**)&xh,  g_xh);
    cudaGetSymbolAddress((void**)&wqt, g_wqt);
    cudaGetSymbolAddress((void**)&wkt, g_wkt);
    cudaGetSymbolAddress((void**)&wvt, g_wvt);
    cudaGetSymbolAddress((void**)&qh,  g_qh);
    cudaGetSymbolAddress((void**)&kh,  g_kh);
    cudaGetSymbolAddress((void**)&vt,  g_vt);
    cudaGetSymbolAddress((void**)&s,   g_s);
    cudaGetSymbolAddress((void**)&ah,  g_ah);

    cudaFuncSetAttribute(gemm1p, cudaFuncAttributeMaxDynamicSharedMemorySize, GEMM_SMEM);

    const int B = BB, S = SS, D = DD;
    const long long MS = (long long)B * S;   // 8192

    // launch 0: x -> fp16 (4-wide)
    conv_h<<<(int)(MS * D / 1024), 256>>>(x, xh);

    // launch 1: merged weight transposes -> fp16
    {
        dim3 tg(D / 32, D / 32, 3);
        transposeW<<<tg, 256>>>(Wq, Wk, Wv, wqt, wkt, wvt);
    }

    // launch 2: fused QKV (1536 tiles) -> q/k fp16 rows, v^T fp16 (fused transpose)
    gemm1p<<<1536, 128, GEMM_SMEM>>>(1, xh, wqt, wkt, wvt, qh, kh, vt);

    // launch 3 (ncu-captured): scores = Q K^T, triangular tile list
    gemm1p<<<136 * B, 128, GEMM_SMEM>>>(2, qh, kh, nullptr, nullptr,
                                        s, nullptr, nullptr);

    // launch 4: vectorized softmax -> fp16 attn
    softmax1<<<B * S, 256>>>(s, ah, S, 0.03125f);

    // launch 5: out = attn @ V (K-clamped, longest tiles first)
    gemm1p<<<16 * 8 * B, 128, GEMM_SMEM>>>(3, ah, vt, nullptr, nullptr,
                                           out, nullptr, nullptr);
}

// round 16
// speedup vs baseline: 2.8255x; 1.8513x over previous
#include <cuda_runtime.h>
#include <cuda_fp16.h>
#include <cstdint>
#include <math.h>

#define BB 4
#define SS 2048
#define DD 1024

// ---------------------------------------------------------------------------
// Scratch (device globals — allocation-free per harness rules)
// All operands plain fp16 (1-pass scheme); fp32 accumulate in MMA.
// Calibrated error model: ~10 incoherent fp16-round components -> ~5.9e-4.
// ---------------------------------------------------------------------------
__device__ __half g_xh [(size_t)BB * SS * DD];       // x fp16    [8192][1024]
__device__ __half g_wqt[(size_t)DD * DD];            // Wq^T fp16 [1024][1024]
__device__ __half g_wkt[(size_t)DD * DD];
__device__ __half g_wvt[(size_t)DD * DD];
__device__ __half g_qh [(size_t)BB * SS * DD];       // q fp16
__device__ __half g_kh [(size_t)BB * SS * DD];       // k fp16
__device__ __half g_vt [(size_t)BB * DD * SS];       // v^T fp16 [b][1024][2048]
__device__ float  g_s  [(size_t)BB * SS * SS];       // raw scores fp32
__device__ __half g_ah [(size_t)BB * SS * SS];       // attn fp16 [b][2048][2048]

// ---------------------------------------------------------------------------
// PTX helpers (compute_103-safe: cp.async, ldmatrix, mma.sync only)
// ---------------------------------------------------------------------------
__device__ __forceinline__ void cp16(uint32_t dst, const void* src) {
    asm volatile("cp.async.cg.shared.global [%0], [%1], 16;\n" :: "r"(dst), "l"(src));
}
__device__ __forceinline__ uint32_t swz128(uint32_t off) { return off ^ ((off >> 3) & 0x70); }

__device__ __forceinline__ void ldsm4(uint32_t& r0, uint32_t& r1, uint32_t& r2, uint32_t& r3,
                                      uint32_t addr) {
    asm volatile("ldmatrix.sync.aligned.m8n8.x4.shared.b16 {%0,%1,%2,%3}, [%4];"
                 : "=r"(r0), "=r"(r1), "=r"(r2), "=r"(r3) : "r"(addr));
}

__device__ __forceinline__ void mma_f16(float c[4], const uint32_t a[4], const uint32_t b0,
                                        const uint32_t b1) {
    asm volatile(
        "mma.sync.aligned.m16n8k16.row.col.f32.f16.f16.f32 "
        "{%0,%1,%2,%3}, {%4,%5,%6,%7}, {%8,%9}, {%0,%1,%2,%3};\n"
        : "+f"(c[0]), "+f"(c[1]), "+f"(c[2]), "+f"(c[3])
        : "r"(a[0]), "r"(a[1]), "r"(a[2]), "r"(a[3]), "r"(b0), "r"(b1));
}

// ---------------------------------------------------------------------------
// 1-pass fp16 GEMM: C[m][n] = sum_k A[m][k] * B[n][k], fp32 accumulate.
// CTA tile 128x128, chunk = 64 k per barrier (A 16KB + B 16KB, swz128 rows),
// 3-stage cp.async, 128 threads = 4 warps of 64x64, ldmatrix.x4 fragments.
// Chunk loads are warp-coalesced: each cp.async instruction covers 4 complete
// 128B rows (8 contiguous lanes per row) -> 100% sector efficiency.
// sched 1: fused QKV — A=x; B = Wq^T/Wk^T/Wv^T (w=t>>9);
//          q/k -> fp16 rows (mode 1); v -> fp16 TRANSPOSED via SMEM bounce
//          (mode 2) directly into v^T [b][d][S] — no separate transpose pass.
// sched 2: scores QK^T — triangular causal list (136/batch); C fp32
// sched 3: attn @ V — K clamped at diagonal block, longest-first; C fp32
// ---------------------------------------------------------------------------
#define STAGE1 32768
#define GEMM_SMEM (3 * STAGE1)       // 98304

__global__ __launch_bounds__(128, 2)
void gemm1p(int sched,
            const __half* __restrict__ A,
            const __half* __restrict__ B0,
            const __half* __restrict__ B1,
            const __half* __restrict__ B2,
            void* __restrict__ C0, void* __restrict__ C1, void* __restrict__ C2)
{
    extern __shared__ __align__(1024) char smem[];
    const uint32_t base0 = (uint32_t)__cvta_generic_to_shared(smem);

    const int tid  = threadIdx.x;
    const int wid  = tid >> 5;
    const int lane = tid & 31;
    const int wm   = wid >> 1;      // 0..1
    const int wn   = wid & 1;       // 0..1

    // ---- decode tile ----
    const int t = blockIdx.x;
    const __half *Ag, *Bg;
    void* Cv;
    int m0, n0, N_C, rowA, rowB, nC, mode;
    if (sched == 1) {                       // fused QKV
        const int w = t >> 9;
        const int r = t & 511;
        m0 = (r >> 3) * 128; n0 = (r & 7) * 128;
        Ag = A;
        Bg = (w == 0) ? B0 : ((w == 1) ? B1 : B2);
        Cv = (w == 0) ? C0 : ((w == 1) ? C1 : C2);
        mode = (w == 2) ? 2 : 1;
        N_C = DD; rowA = DD; rowB = DD; nC = DD / 64;
    } else if (sched == 2) {                // scores, triangular decode
        const int z  = t / 136;
        const int tt = t - z * 136;
        int r = (int)floorf((sqrtf(8.0f * tt + 1.0f) - 1.0f) * 0.5f);
        while ((r + 1) * (r + 2) / 2 <= tt) r++;
        while (r * (r + 1) / 2 > tt) r--;
        const int c = tt - r * (r + 1) / 2;
        m0 = r * 128; n0 = c * 128;
        Ag = A  + (size_t)z * SS * DD;
        Bg = B0 + (size_t)z * SS * DD;
        Cv = (float*)C0 + (size_t)z * SS * SS;
        mode = 0; N_C = SS; rowA = DD; rowB = DD; nC = DD / 64;
    } else {                                // attn @ V, longest-first
        const int m    = 15 - (t >> 5);
        const int rest = t & 31;
        m0 = m * 128; n0 = (rest & 7) * 128;
        const int z = rest >> 3;
        Ag = A  + (size_t)z * SS * SS;
        Bg = B0 + (size_t)z * DD * SS;
        Cv = (float*)C0 + (size_t)z * SS * DD;
        mode = 0; N_C = DD; rowA = SS; rowB = SS;
        nC = min(SS / 64, 2 * m + 2);
    }

    // ldmatrix base offsets (rows of 128B = 64 k-cols, SW128 swizzle per use)
    const int mo  = ((lane >> 3) & 1) * 8 + (lane & 7);
    const int akb = ((lane >> 4) & 1) * 16;
    const int no  = ((lane >> 4) & 1) * 8 + (lane & 7);
    const int bkb = ((lane >> 3) & 1) * 16;
    uint32_t aO[4], bO[4];
    #pragma unroll
    for (int f = 0; f < 4; f++) {
        aO[f] = (uint32_t)((wm * 64 + f * 16 + mo) * 128 + akb);
        bO[f] = (uint32_t)((wn * 64 + f * 16 + no) * 128 + bkb);
    }

    float acc[4][8][4];
    #pragma unroll
    for (int i = 0; i < 4; i++)
        #pragma unroll
        for (int j = 0; j < 8; j++)
            #pragma unroll
            for (int q = 0; q < 4; q++) acc[i][j][q] = 0.0f;

    // chunk loader — warp-coalesced: thread t covers row (t>>3)+16*it,
    // 16B segment (t&7). Each cp.async instruction = 4 full 128B rows.
    const int lseg = tid & 7;
    const int lrow = tid >> 3;          // 0..15
    auto load_chunk = [&](int c) {
        const int st = c % 3;
        const uint32_t aBase = base0 + st * STAGE1;
        const uint32_t bBase = aBase + 16384;
        #pragma unroll
        for (int it = 0; it < 8; it++) {
            const int row = lrow + it * 16;
            const uint32_t so = swz128((uint32_t)(row * 128 + lseg * 16));
            cp16(aBase + so, Ag + (size_t)(m0 + row) * rowA + c * 64 + lseg * 8);
            cp16(bBase + so, Bg + (size_t)(n0 + row) * rowB + c * 64 + lseg * 8);
        }
        asm volatile("cp.async.commit_group;\n");
    };

    load_chunk(0);
    if (nC > 1) load_chunk(1);

    for (int c = 0; c < nC; ++c) {
        if (c + 1 < nC) asm volatile("cp.async.wait_group 1;\n" ::: "memory");
        else            asm volatile("cp.async.wait_group 0;\n" ::: "memory");
        __syncthreads();

        if (c + 2 < nC) load_chunk(c + 2);

        const uint32_t aB = base0 + (c % 3) * STAGE1;
        const uint32_t bB = aB + 16384;

        #pragma unroll
        for (int ks = 0; ks < 4; ks++) {
            const uint32_t kso = (uint32_t)(ks * 32);
            uint32_t af[4][4], bf[4][4];
            #pragma unroll
            for (int f = 0; f < 4; f++)
                ldsm4(af[f][0], af[f][1], af[f][2], af[f][3], aB + swz128(aO[f] + kso));
            #pragma unroll
            for (int f = 0; f < 4; f++)
                ldsm4(bf[f][0], bf[f][1], bf[f][2], bf[f][3], bB + swz128(bO[f] + kso));
            #pragma unroll
            for (int im = 0; im < 4; im++)
                #pragma unroll
                for (int jn = 0; jn < 8; jn++)
                    mma_f16(acc[im][jn], af[im],
                            bf[jn >> 1][(jn & 1) * 2], bf[jn >> 1][(jn & 1) * 2 + 1]);
        }
    }

    // ---- epilogue ----
    if (mode == 2) {
        // v tile: fp16 + transpose via SMEM bounce -> v^T [b][d][S].
        __syncthreads();                       // stage smem now free
        __half* tf = (__half*)smem;            // [128 d-rows][136 pad] halves
        #pragma unroll
        for (int im = 0; im < 4; im++) {
            #pragma unroll
            for (int jn = 0; jn < 8; jn++) {
                #pragma unroll
                for (int hr = 0; hr < 2; hr++) {
                    const int rl = wm * 64 + im * 16 + (lane >> 2) + hr * 8;
                    const int cl = wn * 64 + jn * 8 + (lane & 3) * 2;
                    tf[(size_t)(cl + 0) * 136 + rl] = __float2half(acc[im][jn][hr * 2 + 0]);
                    tf[(size_t)(cl + 1) * 136 + rl] = __float2half(acc[im][jn][hr * 2 + 1]);
                }
            }
        }
        __syncthreads();
        const int b   = m0 >> 11;
        const int s0l = m0 & 2047;
        __half* dst = (__half*)Cv + ((size_t)b * DD + n0 + tid) * SS + s0l;
        const uint4* srcv = (const uint4*)(tf + (size_t)tid * 136);
        uint4* dstv = (uint4*)dst;
        #pragma unroll
        for (int k = 0; k < 16; k++) dstv[k] = srcv[k];
        return;
    }

    #pragma unroll
    for (int im = 0; im < 4; im++) {
        const int r = m0 + wm * 64 + im * 16 + (lane >> 2);
        #pragma unroll
        for (int jn = 0; jn < 8; jn++) {
            const int cc = n0 + wn * 64 + jn * 8 + (lane & 3) * 2;
            if (mode == 0) {
                float* Cg = (float*)Cv;
                *(float2*)(Cg + (size_t)r * N_C + cc)       = make_float2(acc[im][jn][0], acc[im][jn][1]);
                *(float2*)(Cg + (size_t)(r + 8) * N_C + cc) = make_float2(acc[im][jn][2], acc[im][jn][3]);
            } else {
                __half* Cg = (__half*)Cv;
                #pragma unroll
                for (int hr = 0; hr < 2; hr++) {
                    const __half h0 = __float2half(acc[im][jn][hr * 2]);
                    const __half h1 = __float2half(acc[im][jn][hr * 2 + 1]);
                    *(__half2*)(Cg + (size_t)(r + hr * 8) * N_C + cc) = __halves2half2(h0, h1);
                }
            }
        }
    }
}

// ---------------------------------------------------------------------------
// fp32 -> fp16 convert (x), 4 elements per thread
// ---------------------------------------------------------------------------
__global__ __launch_bounds__(256)
void conv_h(const float* __restrict__ src, __half* __restrict__ dst)
{
    const long long idx = ((long long)blockIdx.x * 256 + threadIdx.x) * 4;
    const float4 v = *(const float4*)(src + idx);
    __half2* o = (__half2*)(dst + idx);
    o[0] = __halves2half2(__float2half(v.x), __float2half(v.y));
    o[1] = __halves2half2(__float2half(v.z), __float2half(v.w));
}

// ---------------------------------------------------------------------------
// Merged weight transpose: fp32 [D][D] -> fp16 [D][D], 3 weights via z.
// ---------------------------------------------------------------------------
__global__ __launch_bounds__(256)
void transposeW(const float* __restrict__ s0, const float* __restrict__ s1,
                const float* __restrict__ s2,
                __half* __restrict__ d0, __half* __restrict__ d1,
                __half* __restrict__ d2)
{
    __shared__ float tile[32][33];
    const int z = blockIdx.z;
    const float* src = (z == 0) ? s0 : ((z == 1) ? s1 : s2);
    __half*      dst = (z == 0) ? d0 : ((z == 1) ? d1 : d2);
    const int r0 = blockIdx.y * 32, c0 = blockIdx.x * 32;
    const int tx = threadIdx.x & 31;
    const int ty = threadIdx.x >> 5;

    #pragma unroll
    for (int dy = 0; dy < 32; dy += 8)
        tile[ty + dy][tx] = src[(size_t)(r0 + ty + dy) * DD + c0 + tx];
    __syncthreads();

    #pragma unroll
    for (int dy = 0; dy < 32; dy += 8) {
        const int c = c0 + ty + dy;
        const int r = r0 + tx;
        dst[(size_t)c * DD + r] = __float2half(tile[tx][ty + dy]);
    }
}

// ---------------------------------------------------------------------------
// Vectorized causal softmax -> fp16 attn (arithmetic masking, 4-wide).
// Lz = diagonal-block end (multiple of 128); AV K-clamp never reads past it.
// ---------------------------------------------------------------------------
__global__ __launch_bounds__(256)
void softmax1(const float* __restrict__ Sc, __half* __restrict__ Ah,
              int S, float scale)
{
    const long long row = blockIdx.x;            // b*S + i
    const int i = (int)(row % S);
    const float* p = Sc + row * (long long)S;
    __half* out = Ah + row * (long long)S;
    const int Lz = ((i >> 7) + 1) << 7;

    const int tid  = threadIdx.x;
    const int lane = tid & 31;
    const int wid  = tid >> 5;
    __shared__ float red[32];

    float mx = -INFINITY;
    for (int j = tid * 4; j < Lz; j += 1024) {
        float4 v = *(const float4*)(p + j);
        if (j + 0 > i) v.x = -INFINITY;
        if (j + 1 > i) v.y = -INFINITY;
        if (j + 2 > i) v.z = -INFINITY;
        if (j + 3 > i) v.w = -INFINITY;
        mx = fmaxf(mx, fmaxf(fmaxf(v.x, v.y), fmaxf(v.z, v.w)));
    }
    #pragma unroll
    for (int o = 16; o; o >>= 1) mx = fmaxf(mx, __shfl_xor_sync(0xffffffffu, mx, o));
    if (lane == 0) red[wid] = mx;
    __syncthreads();
    if (tid == 0) {
        float m = red[0];
        #pragma unroll
        for (int w = 1; w < 8; w++) m = fmaxf(m, red[w]);
        red[0] = m;
    }
    __syncthreads();
    mx = red[0];
    __syncthreads();

    float e[8];
    float sum = 0.0f;
    int cnt = 0;
    for (int j = tid * 4; j < Lz; j += 1024) {
        float4 v = *(const float4*)(p + j);
        const float e0 = (j + 0 <= i) ? __expf((v.x - mx) * scale) : 0.0f;
        const float e1 = (j + 1 <= i) ? __expf((v.y - mx) * scale) : 0.0f;
        const float e2 = (j + 2 <= i) ? __expf((v.z - mx) * scale) : 0.0f;
        const float e3 = (j + 3 <= i) ? __expf((v.w - mx) * scale) : 0.0f;
        e[cnt + 0] = e0; e[cnt + 1] = e1; e[cnt + 2] = e2; e[cnt + 3] = e3;
        cnt += 4;
        sum += (e0 + e1) + (e2 + e3);
    }
    #pragma unroll
    for (int o = 16; o; o >>= 1) sum += __shfl_xor_sync(0xffffffffu, sum, o);
    if (lane == 0) red[wid] = sum;
    __syncthreads();
    if (tid == 0) {
        float s = red[0];
        #pragma unroll
        for (int w = 1; w < 8; w++) s += red[w];
        red[0] = s;
    }
    __syncthreads();
    const float inv = 1.0f / red[0];

    cnt = 0;
    for (int j = tid * 4; j < Lz; j += 1024) {
        __half2* o2 = (__half2*)(out + j);
        o2[0] = __halves2half2(__float2half(e[cnt + 0] * inv),
                               __float2half(e[cnt + 1] * inv));
        o2[1] = __halves2half2(__float2half(e[cnt + 2] * inv),
                               __float2half(e[cnt + 3] * inv));
        cnt += 4;
    }
}

// ---------------------------------------------------------------------------
extern "C" void kernel_launch(void* const* d_in, const int* in_sizes, int n_in,
                              void* d_out, int out_size)
{
    (void)in_sizes; (void)n_in; (void)out_size;
    const float* x  = (const float*)d_in[0];
    const float* Wq = (const float*)d_in[1];
    const float* Wk = (const float*)d_in[2];
    const float* Wv = (const float*)d_in[3];
    float* out = (float*)d_out;

    __half *xh, *wqt, *wkt, *wvt, *qh, *kh, *vt, *ah;
    float *s;
    cudaGetSymbolAddress((void**)&xh,  g_xh);
    cudaGetSymbolAddress((void**)&wqt, g_wqt);
    cudaGetSymbolAddress((void**)&wkt, g_wkt);
    cudaGetSymbolAddress((void**)&wvt, g_wvt);
    cudaGetSymbolAddress((void**)&qh,  g_qh);
    cudaGetSymbolAddress((void**)&kh,  g_kh);
    cudaGetSymbolAddress((void**)&vt,  g_vt);
    cudaGetSymbolAddress((void**)&s,   g_s);
    cudaGetSymbolAddress((void**)&ah,  g_ah);

    cudaFuncSetAttribute(gemm1p, cudaFuncAttributeMaxDynamicSharedMemorySize, GEMM_SMEM);

    const int B = BB, S = SS, D = DD;
    const long long MS = (long long)B * S;   // 8192

    // launch 0: x -> fp16 (4-wide)
    conv_h<<<(int)(MS * D / 1024), 256>>>(x, xh);

    // launch 1: merged weight transposes -> fp16
    {
        dim3 tg(D / 32, D / 32, 3);
        transposeW<<<tg, 256>>>(Wq, Wk, Wv, wqt, wkt, wvt);
    }

    // launch 2: fused QKV (1536 tiles) -> q/k fp16 rows, v^T fp16 (fused transpose)
    gemm1p<<<1536, 128, GEMM_SMEM>>>(1, xh, wqt, wkt, wvt, qh, kh, vt);

    // launch 3 (ncu-captured): scores = Q K^T, triangular tile list
    gemm1p<<<136 * B, 128, GEMM_SMEM>>>(2, qh, kh, nullptr, nullptr,
                                        s, nullptr, nullptr);

    // launch 4: vectorized softmax -> fp16 attn
    softmax1<<<B * S, 256>>>(s, ah, S, 0.03125f);

    // launch 5: out = attn @ V (K-clamped, longest tiles first)
    gemm1p<<<16 * 8 * B, 128, GEMM_SMEM>>>(3, ah, vt, nullptr, nullptr,
                                           out, nullptr, nullptr);
}